// round 1
// baseline (speedup 1.0000x reference)
#include <cuda_runtime.h>
#include <cstdint>
#include <cstddef>

// Problem dims
#define T_LEN 4096
#define HD    512
#define G3    1536          // 3*HD
#define NC    4880

// ---------------- scratch (static device memory; no allocations) -------------
__device__ float g_visit[(size_t)T_LEN * HD];        // 8 MB
__device__ float g_gi[(size_t)T_LEN * G3];           // 25 MB
__device__ float g_hs[(size_t)T_LEN * HD];           // 8 MB
__device__ float g_logits[T_LEN];
__device__ float g_part[32 * HD];

// ---------------- f32x2 packed math (sm_100+) --------------------------------
#define FMA2(d, a, b, c) \
    asm("fma.rn.f32x2 %0, %1, %2, %3;" : "=l"(d) : "l"(a), "l"(b), "l"(c))
#define PACK2(d, lo, hi) \
    asm("mov.b64 %0, {%1, %2};" : "=l"(d) : "f"(lo), "f"(hi))
#define UNPACK2(lo, hi, d) \
    asm("mov.b64 {%0, %1}, %2;" : "=f"(lo), "=f"(hi) : "l"(d))

// =============================================================================
// GEMM 1: g_visit[t, d] = sum_c H[c, t] * X[c, d]
//   M = 4096 (t), N = 512 (d), K = 4880 (c).  A[m,k] = H[k*4096 + m] (K-major,
//   contiguous in m -> natural load).  B[k,n] = X[k*512 + n] row-major.
//   128x128x8 tile, 256 threads, 8x8 microtile with packed f32x2 FMA.
// =============================================================================
__global__ __launch_bounds__(256) void gemm_visit(const float* __restrict__ Hm,
                                                  const float* __restrict__ X) {
    __shared__ float As[8][128];
    __shared__ float Bs[8][128];
    const int tid = threadIdx.x;
    const int m0 = blockIdx.y * 128;
    const int n0 = blockIdx.x * 128;
    const int tx = tid & 15, ty = tid >> 4;
    const int lk = tid >> 5;            // 0..7
    const int lm = (tid & 31) * 4;      // 0..124

    unsigned long long acc[8][4];
#pragma unroll
    for (int i = 0; i < 8; i++)
#pragma unroll
        for (int j = 0; j < 4; j++) acc[i][j] = 0ull;

    for (int k0 = 0; k0 < NC; k0 += 8) {
        *(float4*)&As[lk][lm] = *(const float4*)&Hm[(size_t)(k0 + lk) * T_LEN + m0 + lm];
        *(float4*)&Bs[lk][lm] = *(const float4*)&X[(size_t)(k0 + lk) * HD + n0 + lm];
        __syncthreads();
#pragma unroll
        for (int kt = 0; kt < 8; kt++) {
            float a[8];
            unsigned long long b2[4];
#pragma unroll
            for (int i = 0; i < 8; i++) a[i] = As[kt][ty * 8 + i];
#pragma unroll
            for (int j = 0; j < 4; j++)
                b2[j] = *(const unsigned long long*)&Bs[kt][tx * 8 + 2 * j];
#pragma unroll
            for (int i = 0; i < 8; i++) {
                unsigned long long ad;
                PACK2(ad, a[i], a[i]);
#pragma unroll
                for (int j = 0; j < 4; j++) FMA2(acc[i][j], ad, b2[j], acc[i][j]);
            }
        }
        __syncthreads();
    }
#pragma unroll
    for (int i = 0; i < 8; i++)
#pragma unroll
        for (int j = 0; j < 4; j++) {
            float lo, hi;
            UNPACK2(lo, hi, acc[i][j]);
            size_t base = (size_t)(m0 + ty * 8 + i) * HD + n0 + tx * 8 + 2 * j;
            g_visit[base] = lo;
            g_visit[base + 1] = hi;
        }
}

// =============================================================================
// GEMM 2: g_gi[t, r] = sum_d g_visit[t, d] * W_ih[r, d] + b_ih[r]
//   M = 4096, N = 1536, K = 512.  Both A and B need transpose-on-load.
// =============================================================================
__global__ __launch_bounds__(256) void gemm_gi(const float* __restrict__ Wih,
                                               const float* __restrict__ bih) {
    __shared__ float As[8][128];
    __shared__ float Bs[8][128];
    const int tid = threadIdx.x;
    const int m0 = blockIdx.y * 128;
    const int n0 = blockIdx.x * 128;
    const int tx = tid & 15, ty = tid >> 4;
    const int lrow = tid >> 1;          // 0..127  (m or n)
    const int q0 = (tid & 1) * 4;       // 0 or 4  (k sub-offset)

    unsigned long long acc[8][4];
#pragma unroll
    for (int i = 0; i < 8; i++)
#pragma unroll
        for (int j = 0; j < 4; j++) acc[i][j] = 0ull;

    for (int k0 = 0; k0 < HD; k0 += 8) {
        float4 va = *(const float4*)&g_visit[(size_t)(m0 + lrow) * HD + k0 + q0];
        float4 vb = *(const float4*)&Wih[(size_t)(n0 + lrow) * HD + k0 + q0];
        As[q0 + 0][lrow] = va.x; As[q0 + 1][lrow] = va.y;
        As[q0 + 2][lrow] = va.z; As[q0 + 3][lrow] = va.w;
        Bs[q0 + 0][lrow] = vb.x; Bs[q0 + 1][lrow] = vb.y;
        Bs[q0 + 2][lrow] = vb.z; Bs[q0 + 3][lrow] = vb.w;
        __syncthreads();
#pragma unroll
        for (int kt = 0; kt < 8; kt++) {
            float a[8];
            unsigned long long b2[4];
#pragma unroll
            for (int i = 0; i < 8; i++) a[i] = As[kt][ty * 8 + i];
#pragma unroll
            for (int j = 0; j < 4; j++)
                b2[j] = *(const unsigned long long*)&Bs[kt][tx * 8 + 2 * j];
#pragma unroll
            for (int i = 0; i < 8; i++) {
                unsigned long long ad;
                PACK2(ad, a[i], a[i]);
#pragma unroll
                for (int j = 0; j < 4; j++) FMA2(acc[i][j], ad, b2[j], acc[i][j]);
            }
        }
        __syncthreads();
    }
#pragma unroll
    for (int i = 0; i < 8; i++)
#pragma unroll
        for (int j = 0; j < 4; j++) {
            float lo, hi;
            UNPACK2(lo, hi, acc[i][j]);
            int n = n0 + tx * 8 + 2 * j;
            size_t base = (size_t)(m0 + ty * 8 + i) * G3 + n;
            g_gi[base] = lo + bih[n];
            g_gi[base + 1] = hi + bih[n + 1];
        }
}

// =============================================================================
// GRU scan: 16-CTA cluster, 512 threads/CTA, persistent over 4096 steps.
//   CTA `rank` owns hidden dims [rank*32, rank*32+32)  -> 96 rows of W_hh.
//   Warp w owns local rows 6w..6w+5; lane l owns k in [16l, 16l+16)
//   -> 96 register-resident weights per thread (48 f32x2 regs).
//   h (512 floats) lives in smem, double-buffered; each CTA's 32 new values
//   are pushed to all 16 CTAs' smem via DSMEM stores; barrier.cluster / step.
// =============================================================================
__global__ __launch_bounds__(512, 1) void k_gru(const float* __restrict__ Whh,
                                                const float* __restrict__ bhh) {
    __shared__ float h_buf[2][HD];
    __shared__ float gh_sm[96];
    const int tid = threadIdx.x;
    const int warp = tid >> 5, lane = tid & 31;
    unsigned int rank;
    asm("mov.u32 %0, %%cluster_ctarank;" : "=r"(rank));

    for (int i = tid; i < 2 * HD; i += 512) ((float*)h_buf)[i] = 0.f;

    // Load the 96 weights (as 48 packed f32x2) for this thread.
    unsigned long long Wr[6][8];
#pragma unroll
    for (int r = 0; r < 6; r++) {
        const int lr = warp * 6 + r;
        const int grow = (lr >> 5) * HD + (int)rank * 32 + (lr & 31);
        const float* wp = Whh + (size_t)grow * HD + lane * 16;
#pragma unroll
        for (int i = 0; i < 8; i++)
            Wr[r][i] = *(const unsigned long long*)(wp + 2 * i);
    }

    float bh_r = 0.f, bh_z = 0.f, bh_n = 0.f;
    if (tid < 32) {
        const int d = (int)rank * 32 + tid;
        bh_r = bhh[d];
        bh_z = bhh[HD + d];
        bh_n = bhh[2 * HD + d];
    }

    unsigned int hbase;
    asm("{ .reg .u64 t; cvta.to.shared.u64 t, %1; cvt.u32.u64 %0, t; }"
        : "=r"(hbase) : "l"(&h_buf[0][0]));

    __syncthreads();
    asm volatile("barrier.cluster.arrive.aligned;\n\tbarrier.cluster.wait.aligned;" ::: "memory");

    int p = 0;
    const float* gp = g_gi + (int)rank * 32 + tid;   // valid when tid < 32
    for (int t = 0; t < T_LEN; t++) {
        float gi_r = 0.f, gi_z = 0.f, gi_n = 0.f;
        if (tid < 32) {                 // prefetch early, consumed after FMA phase
            gi_r = __ldg(gp);
            gi_z = __ldg(gp + HD);
            gi_n = __ldg(gp + 2 * HD);
        }

        // --- FMA phase: gh partials from register weights × smem h ---
        unsigned long long acc[6];
#pragma unroll
        for (int r = 0; r < 6; r++) acc[r] = 0ull;
        const float* hp = &h_buf[p][lane * 16];
#pragma unroll
        for (int i = 0; i < 8; i++) {
            unsigned long long h2 = *(const unsigned long long*)(hp + 2 * i);
#pragma unroll
            for (int r = 0; r < 6; r++) FMA2(acc[r], Wr[r][i], h2, acc[r]);
        }
        // --- reduce 32 lanes per row, deposit row sums in smem ---
#pragma unroll
        for (int r = 0; r < 6; r++) {
            float lo, hi;
            UNPACK2(lo, hi, acc[r]);
            float s = lo + hi;
#pragma unroll
            for (int off = 16; off; off >>= 1)
                s += __shfl_xor_sync(0xffffffffu, s, off);
            if (lane == r) gh_sm[warp * 6 + r] = s;
        }
        __syncthreads();

        // --- gates + update + DSMEM broadcast (warp 0 only) ---
        if (tid < 32) {
            const int j = tid;
            float xr = gh_sm[j] + gi_r + bh_r;
            float xz = gh_sm[32 + j] + gi_z + bh_z;
            float dn = gh_sm[64 + j];
            float rr = 1.f / (1.f + __expf(-xr));
            float zz = 1.f / (1.f + __expf(-xz));
            float hold = h_buf[p][(int)rank * 32 + j];
            float nn = tanhf(gi_n + rr * (dn + bh_n));
            float hnew = (1.f - zz) * nn + zz * hold;
            g_hs[(size_t)t * HD + (int)rank * 32 + j] = hnew;
            unsigned int dst =
                hbase + (unsigned int)(((p ^ 1) * HD + (int)rank * 32 + j) * 4);
#pragma unroll
            for (int c = 0; c < 16; c++) {
                unsigned int rem;
                asm("mapa.shared::cluster.u32 %0, %1, %2;"
                    : "=r"(rem) : "r"(dst), "r"(c));
                asm volatile("st.shared::cluster.f32 [%0], %1;"
                             :: "r"(rem), "f"(hnew) : "memory");
            }
        }
        // release our DSMEM stores / acquire everyone else's
        asm volatile("barrier.cluster.arrive.aligned;\n\tbarrier.cluster.wait.aligned;" ::: "memory");
        p ^= 1;
        gp += G3;
    }
}

// =============================================================================
// Attention epilogue
// =============================================================================
__global__ void k_logits(const float* __restrict__ watt) {
    const int t = blockIdx.x * 8 + (threadIdx.x >> 5);
    const int lane = threadIdx.x & 31;
    float s = 0.f;
#pragma unroll
    for (int i = 0; i < 16; i++)
        s += g_hs[(size_t)t * HD + lane + 32 * i] * watt[lane + 32 * i];
#pragma unroll
    for (int off = 16; off; off >>= 1) s += __shfl_xor_sync(0xffffffffu, s, off);
    if (lane == 0) g_logits[t] = s;
}

__global__ void k_softmax() {
    __shared__ float red[32];
    __shared__ float bcast;
    const int tid = threadIdx.x, lane = tid & 31, w = tid >> 5;
    float v[4], m = -1e30f;
#pragma unroll
    for (int i = 0; i < 4; i++) {
        v[i] = g_logits[tid + 1024 * i];
        m = fmaxf(m, v[i]);
    }
#pragma unroll
    for (int off = 16; off; off >>= 1)
        m = fmaxf(m, __shfl_xor_sync(0xffffffffu, m, off));
    if (lane == 0) red[w] = m;
    __syncthreads();
    if (w == 0) {
        float x = red[lane];
#pragma unroll
        for (int off = 16; off; off >>= 1)
            x = fmaxf(x, __shfl_xor_sync(0xffffffffu, x, off));
        if (lane == 0) bcast = x;
    }
    __syncthreads();
    const float M = bcast;
    __syncthreads();
    float s = 0.f;
#pragma unroll
    for (int i = 0; i < 4; i++) {
        v[i] = __expf(v[i] - M);
        s += v[i];
    }
#pragma unroll
    for (int off = 16; off; off >>= 1) s += __shfl_xor_sync(0xffffffffu, s, off);
    if (lane == 0) red[w] = s;
    __syncthreads();
    if (w == 0) {
        float x = red[lane];
#pragma unroll
        for (int off = 16; off; off >>= 1) x += __shfl_xor_sync(0xffffffffu, x, off);
        if (lane == 0) bcast = 1.f / x;
    }
    __syncthreads();
    const float inv = bcast;
#pragma unroll
    for (int i = 0; i < 4; i++) g_logits[tid + 1024 * i] = v[i] * inv;
}

__global__ void k_wsum() {
    const int d = threadIdx.x;
    const int b = blockIdx.x;
    float acc = 0.f;
    for (int t = b * 128; t < b * 128 + 128; t++)
        acc += g_logits[t] * g_hs[(size_t)t * HD + d];
    g_part[b * HD + d] = acc;
}

__global__ void k_final(float* __restrict__ out) {
    const int d = threadIdx.x;
    float acc = 0.f;
#pragma unroll
    for (int b = 0; b < 32; b++) acc += g_part[b * HD + d];
    out[d] = acc;
}

// =============================================================================
// Launch
// =============================================================================
extern "C" void kernel_launch(void* const* d_in, const int* in_sizes, int n_in,
                              void* d_out, int out_size) {
    const float* H    = (const float*)d_in[0];
    // d_in[1] = TE (unused)
    const float* Xemb = (const float*)d_in[2];
    const float* Wih  = (const float*)d_in[3];
    const float* Whh  = (const float*)d_in[4];
    const float* bih  = (const float*)d_in[5];
    const float* bhh  = (const float*)d_in[6];
    const float* watt = (const float*)d_in[7];
    float* out = (float*)d_out;

    gemm_visit<<<dim3(4, 32), 256>>>(H, Xemb);
    gemm_gi<<<dim3(12, 32), 256>>>(Wih, bih);

    // 16-CTA cluster GRU scan
    cudaFuncSetAttribute(k_gru, cudaFuncAttributeNonPortableClusterSizeAllowed, 1);
    cudaLaunchConfig_t cfg = {};
    cfg.gridDim = dim3(16, 1, 1);
    cfg.blockDim = dim3(512, 1, 1);
    cfg.dynamicSmemBytes = 0;
    cfg.stream = 0;
    cudaLaunchAttribute attrs[1];
    attrs[0].id = cudaLaunchAttributeClusterDimension;
    attrs[0].val.clusterDim.x = 16;
    attrs[0].val.clusterDim.y = 1;
    attrs[0].val.clusterDim.z = 1;
    cfg.attrs = attrs;
    cfg.numAttrs = 1;
    cudaLaunchKernelEx(&cfg, k_gru, Whh, bhh);

    k_logits<<<512, 256>>>(watt);
    k_softmax<<<1, 1024>>>();
    k_wsum<<<32, 512>>>();
    k_final<<<1, 512>>>(out);
}

// round 3
// speedup vs baseline: 1.1653x; 1.1653x over previous
#include <cuda_runtime.h>
#include <cstdint>
#include <cstddef>

// Problem dims
#define T_LEN 4096
#define HD    512
#define G3    1536          // 3*HD
#define NC    4880

// ---------------- scratch (static device memory; no allocations) -------------
__device__ float g_visit[(size_t)T_LEN * HD];        // 8 MB
__device__ float g_gi[(size_t)T_LEN * G3];           // 25 MB
__device__ float g_hs[(size_t)T_LEN * HD];           // 8 MB
__device__ float g_logits[T_LEN];
__device__ float g_part[32 * HD];

// ---------------- f32x2 packed math (sm_100+) --------------------------------
#define FMA2(d, a, b, c) \
    asm("fma.rn.f32x2 %0, %1, %2, %3;" : "=l"(d) : "l"(a), "l"(b), "l"(c))
#define PACK2(d, lo, hi) \
    asm("mov.b64 %0, {%1, %2};" : "=l"(d) : "f"(lo), "f"(hi))
#define UNPACK2(lo, hi, d) \
    asm("mov.b64 {%0, %1}, %2;" : "=f"(lo), "=f"(hi) : "l"(d))

// =============================================================================
// GEMM 1: g_visit[t, d] = sum_c H[c, t] * X[c, d]
//   M = 4096 (t), N = 512 (d), K = 4880 (c).
//   128x128x8 tile, 256 threads, 8x8 microtile with packed f32x2 FMA.
// =============================================================================
__global__ __launch_bounds__(256) void gemm_visit(const float* __restrict__ Hm,
                                                  const float* __restrict__ X) {
    __shared__ float As[8][128];
    __shared__ float Bs[8][128];
    const int tid = threadIdx.x;
    const int m0 = blockIdx.y * 128;
    const int n0 = blockIdx.x * 128;
    const int tx = tid & 15, ty = tid >> 4;
    const int lk = tid >> 5;            // 0..7
    const int lm = (tid & 31) * 4;      // 0..124

    unsigned long long acc[8][4];
#pragma unroll
    for (int i = 0; i < 8; i++)
#pragma unroll
        for (int j = 0; j < 4; j++) acc[i][j] = 0ull;

    for (int k0 = 0; k0 < NC; k0 += 8) {
        *(float4*)&As[lk][lm] = *(const float4*)&Hm[(size_t)(k0 + lk) * T_LEN + m0 + lm];
        *(float4*)&Bs[lk][lm] = *(const float4*)&X[(size_t)(k0 + lk) * HD + n0 + lm];
        __syncthreads();
#pragma unroll
        for (int kt = 0; kt < 8; kt++) {
            float a[8];
            unsigned long long b2[4];
#pragma unroll
            for (int i = 0; i < 8; i++) a[i] = As[kt][ty * 8 + i];
#pragma unroll
            for (int j = 0; j < 4; j++)
                b2[j] = *(const unsigned long long*)&Bs[kt][tx * 8 + 2 * j];
#pragma unroll
            for (int i = 0; i < 8; i++) {
                unsigned long long ad;
                PACK2(ad, a[i], a[i]);
#pragma unroll
                for (int j = 0; j < 4; j++) FMA2(acc[i][j], ad, b2[j], acc[i][j]);
            }
        }
        __syncthreads();
    }
#pragma unroll
    for (int i = 0; i < 8; i++)
#pragma unroll
        for (int j = 0; j < 4; j++) {
            float lo, hi;
            UNPACK2(lo, hi, acc[i][j]);
            size_t base = (size_t)(m0 + ty * 8 + i) * HD + n0 + tx * 8 + 2 * j;
            g_visit[base] = lo;
            g_visit[base + 1] = hi;
        }
}

// =============================================================================
// GEMM 2: g_gi[t, r] = sum_d g_visit[t, d] * W_ih[r, d] + b_ih[r]
//   M = 4096, N = 1536, K = 512.
// =============================================================================
__global__ __launch_bounds__(256) void gemm_gi(const float* __restrict__ Wih,
                                               const float* __restrict__ bih) {
    __shared__ float As[8][128];
    __shared__ float Bs[8][128];
    const int tid = threadIdx.x;
    const int m0 = blockIdx.y * 128;
    const int n0 = blockIdx.x * 128;
    const int tx = tid & 15, ty = tid >> 4;
    const int lrow = tid >> 1;          // 0..127  (m or n)
    const int q0 = (tid & 1) * 4;       // 0 or 4  (k sub-offset)

    unsigned long long acc[8][4];
#pragma unroll
    for (int i = 0; i < 8; i++)
#pragma unroll
        for (int j = 0; j < 4; j++) acc[i][j] = 0ull;

    for (int k0 = 0; k0 < HD; k0 += 8) {
        float4 va = *(const float4*)&g_visit[(size_t)(m0 + lrow) * HD + k0 + q0];
        float4 vb = *(const float4*)&Wih[(size_t)(n0 + lrow) * HD + k0 + q0];
        As[q0 + 0][lrow] = va.x; As[q0 + 1][lrow] = va.y;
        As[q0 + 2][lrow] = va.z; As[q0 + 3][lrow] = va.w;
        Bs[q0 + 0][lrow] = vb.x; Bs[q0 + 1][lrow] = vb.y;
        Bs[q0 + 2][lrow] = vb.z; Bs[q0 + 3][lrow] = vb.w;
        __syncthreads();
#pragma unroll
        for (int kt = 0; kt < 8; kt++) {
            float a[8];
            unsigned long long b2[4];
#pragma unroll
            for (int i = 0; i < 8; i++) a[i] = As[kt][ty * 8 + i];
#pragma unroll
            for (int j = 0; j < 4; j++)
                b2[j] = *(const unsigned long long*)&Bs[kt][tx * 8 + 2 * j];
#pragma unroll
            for (int i = 0; i < 8; i++) {
                unsigned long long ad;
                PACK2(ad, a[i], a[i]);
#pragma unroll
                for (int j = 0; j < 4; j++) FMA2(acc[i][j], ad, b2[j], acc[i][j]);
            }
        }
        __syncthreads();
    }
#pragma unroll
    for (int i = 0; i < 8; i++)
#pragma unroll
        for (int j = 0; j < 4; j++) {
            float lo, hi;
            UNPACK2(lo, hi, acc[i][j]);
            int n = n0 + tx * 8 + 2 * j;
            size_t base = (size_t)(m0 + ty * 8 + i) * G3 + n;
            g_gi[base] = lo + bih[n];
            g_gi[base + 1] = hi + bih[n + 1];
        }
}

// =============================================================================
// GRU scan: 16-CTA cluster, 512 threads/CTA, persistent over 4096 steps.
//   CTA `rank` owns hidden dims [rank*32, rank*32+32) -> 96 rows of W_hh.
//   Warp w owns local rows 6w..6w+5.
//   Lane l owns k in {l, l+32, ..., l+480}  (stride-32: conflict-free LDS,
//   all 32 lanes hit distinct banks).  FMA2 pairs (k=l+64i, k=l+64i+32).
//   96 register-resident weights per thread (48 f32x2 regs).
//   h (512 floats) lives in smem, double-buffered; each CTA's 32 new values
//   are pushed to all 16 CTAs' smem via DSMEM stores; barrier.cluster / step.
// =============================================================================
__global__ __launch_bounds__(512, 1) void k_gru(const float* __restrict__ Whh,
                                                const float* __restrict__ bhh) {
    __shared__ float h_buf[2][HD];
    __shared__ float gh_sm[96];
    const int tid = threadIdx.x;
    const int warp = tid >> 5, lane = tid & 31;
    unsigned int rank;
    asm("mov.u32 %0, %%cluster_ctarank;" : "=r"(rank));

    for (int i = tid; i < 2 * HD; i += 512) ((float*)h_buf)[i] = 0.f;

    // Load the 96 weights (as 48 packed f32x2) for this thread, in the
    // stride-32 k-permutation: pair i = (k = lane+64i, k = lane+64i+32).
    unsigned long long Wr[6][8];
#pragma unroll
    for (int r = 0; r < 6; r++) {
        const int lr = warp * 6 + r;
        const int grow = (lr >> 5) * HD + (int)rank * 32 + (lr & 31);
        const float* wp = Whh + (size_t)grow * HD;
#pragma unroll
        for (int i = 0; i < 8; i++) {
            float wlo = wp[lane + 64 * i];
            float whi = wp[lane + 64 * i + 32];
            PACK2(Wr[r][i], wlo, whi);
        }
    }

    float bh_r = 0.f, bh_z = 0.f, bh_n = 0.f;
    if (tid < 32) {
        const int d = (int)rank * 32 + tid;
        bh_r = bhh[d];
        bh_z = bhh[HD + d];
        bh_n = bhh[2 * HD + d];
    }

    unsigned int hbase;
    asm("{ .reg .u64 t; cvta.to.shared.u64 t, %1; cvt.u32.u64 %0, t; }"
        : "=r"(hbase) : "l"(&h_buf[0][0]));

    __syncthreads();
    asm volatile("barrier.cluster.arrive.aligned;\n\tbarrier.cluster.wait.aligned;" ::: "memory");

    int p = 0;
    const float* gp = g_gi + (int)rank * 32 + tid;   // valid when tid < 32
    for (int t = 0; t < T_LEN; t++) {
        float gi_r = 0.f, gi_z = 0.f, gi_n = 0.f;
        if (tid < 32) {                 // prefetch early, consumed after FMA phase
            gi_r = __ldg(gp);
            gi_z = __ldg(gp + HD);
            gi_n = __ldg(gp + 2 * HD);
        }

        // --- FMA phase: gh partials from register weights × smem h ---
        unsigned long long acc[6];
#pragma unroll
        for (int r = 0; r < 6; r++) acc[r] = 0ull;
        const float* hp = &h_buf[p][lane];
#pragma unroll
        for (int i = 0; i < 8; i++) {
            float hlo = hp[64 * i];        // bank = lane  (conflict-free)
            float hhi = hp[64 * i + 32];   // bank = lane  (conflict-free)
            unsigned long long h2;
            PACK2(h2, hlo, hhi);
#pragma unroll
            for (int r = 0; r < 6; r++) FMA2(acc[r], Wr[r][i], h2, acc[r]);
        }
        // --- reduce 32 lanes per row, deposit row sums in smem ---
#pragma unroll
        for (int r = 0; r < 6; r++) {
            float lo, hi;
            UNPACK2(lo, hi, acc[r]);
            float s = lo + hi;
#pragma unroll
            for (int off = 16; off; off >>= 1)
                s += __shfl_xor_sync(0xffffffffu, s, off);
            if (lane == r) gh_sm[warp * 6 + r] = s;
        }
        __syncthreads();

        // --- gates + update + DSMEM broadcast (warp 0 only) ---
        if (tid < 32) {
            const int j = tid;
            float xr = gh_sm[j] + gi_r + bh_r;
            float xz = gh_sm[32 + j] + gi_z + bh_z;
            float dn = gh_sm[64 + j];
            float rr = 1.f / (1.f + __expf(-xr));
            float zz = 1.f / (1.f + __expf(-xz));
            float hold = h_buf[p][(int)rank * 32 + j];
            float nn = tanhf(gi_n + rr * (dn + bh_n));
            float hnew = (1.f - zz) * nn + zz * hold;
            g_hs[(size_t)t * HD + (int)rank * 32 + j] = hnew;
            unsigned int dst =
                hbase + (unsigned int)(((p ^ 1) * HD + (int)rank * 32 + j) * 4);
#pragma unroll
            for (int c = 0; c < 16; c++) {
                unsigned int rem;
                asm("mapa.shared::cluster.u32 %0, %1, %2;"
                    : "=r"(rem) : "r"(dst), "r"(c));
                asm volatile("st.shared::cluster.f32 [%0], %1;"
                             :: "r"(rem), "f"(hnew) : "memory");
            }
        }
        // release our DSMEM stores / acquire everyone else's
        asm volatile("barrier.cluster.arrive.aligned;\n\tbarrier.cluster.wait.aligned;" ::: "memory");
        p ^= 1;
        gp += G3;
    }
}

// =============================================================================
// Attention epilogue
// =============================================================================
__global__ void k_logits(const float* __restrict__ watt) {
    const int t = blockIdx.x * 8 + (threadIdx.x >> 5);
    const int lane = threadIdx.x & 31;
    float s = 0.f;
#pragma unroll
    for (int i = 0; i < 16; i++)
        s += g_hs[(size_t)t * HD + lane + 32 * i] * watt[lane + 32 * i];
#pragma unroll
    for (int off = 16; off; off >>= 1) s += __shfl_xor_sync(0xffffffffu, s, off);
    if (lane == 0) g_logits[t] = s;
}

__global__ void k_softmax() {
    __shared__ float red[32];
    __shared__ float bcast;
    const int tid = threadIdx.x, lane = tid & 31, w = tid >> 5;
    float v[4], m = -1e30f;
#pragma unroll
    for (int i = 0; i < 4; i++) {
        v[i] = g_logits[tid + 1024 * i];
        m = fmaxf(m, v[i]);
    }
#pragma unroll
    for (int off = 16; off; off >>= 1)
        m = fmaxf(m, __shfl_xor_sync(0xffffffffu, m, off));
    if (lane == 0) red[w] = m;
    __syncthreads();
    if (w == 0) {
        float x = red[lane];
#pragma unroll
        for (int off = 16; off; off >>= 1)
            x = fmaxf(x, __shfl_xor_sync(0xffffffffu, x, off));
        if (lane == 0) bcast = x;
    }
    __syncthreads();
    const float M = bcast;
    __syncthreads();
    float s = 0.f;
#pragma unroll
    for (int i = 0; i < 4; i++) {
        v[i] = __expf(v[i] - M);
        s += v[i];
    }
#pragma unroll
    for (int off = 16; off; off >>= 1) s += __shfl_xor_sync(0xffffffffu, s, off);
    if (lane == 0) red[w] = s;
    __syncthreads();
    if (w == 0) {
        float x = red[lane];
#pragma unroll
        for (int off = 16; off; off >>= 1) x += __shfl_xor_sync(0xffffffffu, x, off);
        if (lane == 0) bcast = 1.f / x;
    }
    __syncthreads();
    const float inv = bcast;
#pragma unroll
    for (int i = 0; i < 4; i++) g_logits[tid + 1024 * i] = v[i] * inv;
}

__global__ void k_wsum() {
    const int d = threadIdx.x;
    const int b = blockIdx.x;
    float acc = 0.f;
    for (int t = b * 128; t < b * 128 + 128; t++)
        acc += g_logits[t] * g_hs[(size_t)t * HD + d];
    g_part[b * HD + d] = acc;
}

__global__ void k_final(float* __restrict__ out) {
    const int d = threadIdx.x;
    float acc = 0.f;
#pragma unroll
    for (int b = 0; b < 32; b++) acc += g_part[b * HD + d];
    out[d] = acc;
}

// =============================================================================
// Launch
// =============================================================================
extern "C" void kernel_launch(void* const* d_in, const int* in_sizes, int n_in,
                              void* d_out, int out_size) {
    const float* H    = (const float*)d_in[0];
    // d_in[1] = TE (unused)
    const float* Xemb = (const float*)d_in[2];
    const float* Wih  = (const float*)d_in[3];
    const float* Whh  = (const float*)d_in[4];
    const float* bih  = (const float*)d_in[5];
    const float* bhh  = (const float*)d_in[6];
    const float* watt = (const float*)d_in[7];
    float* out = (float*)d_out;

    gemm_visit<<<dim3(4, 32), 256>>>(H, Xemb);
    gemm_gi<<<dim3(12, 32), 256>>>(Wih, bih);

    // 16-CTA cluster GRU scan
    cudaFuncSetAttribute(k_gru, cudaFuncAttributeNonPortableClusterSizeAllowed, 1);
    cudaLaunchConfig_t cfg = {};
    cfg.gridDim = dim3(16, 1, 1);
    cfg.blockDim = dim3(512, 1, 1);
    cfg.dynamicSmemBytes = 0;
    cfg.stream = 0;
    cudaLaunchAttribute attrs[1];
    attrs[0].id = cudaLaunchAttributeClusterDimension;
    attrs[0].val.clusterDim.x = 16;
    attrs[0].val.clusterDim.y = 1;
    attrs[0].val.clusterDim.z = 1;
    cfg.attrs = attrs;
    cfg.numAttrs = 1;
    cudaLaunchKernelEx(&cfg, k_gru, Whh, bhh);

    k_logits<<<512, 256>>>(watt);
    k_softmax<<<1, 1024>>>();
    k_wsum<<<32, 512>>>();
    k_final<<<1, 512>>>(out);
}